// round 11
// baseline (speedup 1.0000x reference)
#include <cuda_runtime.h>
#include <cuda_bf16.h>
#include <cstdint>

#define B_      16
#define N_SP    2048
#define N_TM    64
#define M_OUT   2112
#define M_PAD   2176
#define KD      64
#define TILE    128
#define NTILES  17
#define NPAIRS  153      // 17*18/2 upper-triangular tile pairs

// Scratch: bf16 hi/lo splits of concatenated+padded node embeddings.
__device__ __nv_bfloat16 g_hi[B_ * M_PAD * KD];
__device__ __nv_bfloat16 g_lo[B_ * M_PAD * KD];

// ---------------------------------------------------------------------------
// Pass 1: fp32 -> bf16 hi/lo split, concat(spatial, temporal), zero-pad rows.
// 8 elements (2 float4) per thread; one uint4 store per output array.
// ---------------------------------------------------------------------------
__global__ void convert_split_kernel(const float4* __restrict__ sp,
                                     const float4* __restrict__ tp) {
    // PDL: allow the dependent gram kernel to begin its prologue now.
    cudaTriggerProgrammaticLaunchCompletion();

    const int TOT2 = B_ * M_PAD * 8;     // uint4-granularity work items
    int idx = blockIdx.x * blockDim.x + threadIdx.x;
    if (idx >= TOT2) return;
    int kq2 = idx & 7;                   // 8-elem segment within 64-elem row
    int row = (idx >> 3) % M_PAD;
    int b   = idx / (M_PAD * 8);

    float4 x0 = make_float4(0.f, 0.f, 0.f, 0.f), x1 = x0;
    if (row < N_SP) {
        const float4* p = sp + ((long)b * N_SP + row) * 16 + kq2 * 2;
        x0 = p[0]; x1 = p[1];
    } else if (row < M_OUT) {
        const float4* p = tp + ((long)b * N_TM + (row - N_SP)) * 16 + kq2 * 2;
        x0 = p[0]; x1 = p[1];
    }

    float xf[8] = {x0.x, x0.y, x0.z, x0.w, x1.x, x1.y, x1.z, x1.w};
    union { __nv_bfloat16 h[8]; uint4 u; } uh;
    union { __nv_bfloat16 h[8]; uint4 u; } ul;
#pragma unroll
    for (int i = 0; i < 8; i++) {
        __nv_bfloat16 h = __float2bfloat16(xf[i]);
        float lo = xf[i] - __bfloat162float(h);
        uh.h[i] = h;
        ul.h[i] = __float2bfloat16(lo);
    }
    reinterpret_cast<uint4*>(g_hi)[idx] = uh.u;
    reinterpret_cast<uint4*>(g_lo)[idx] = ul.u;
}

// ---------------------------------------------------------------------------
// PTX helpers (portable compute_103: mma.sync + ldmatrix + cp.async + tanh)
// ---------------------------------------------------------------------------
__device__ __forceinline__ uint32_t smem_u32(const void* p) {
    uint32_t a;
    asm("{ .reg .u64 t; cvta.to.shared.u64 t, %1; cvt.u32.u64 %0, t; }"
        : "=r"(a) : "l"(p));
    return a;
}

__device__ __forceinline__ void cp_async16(uint32_t saddr, const void* gptr) {
    asm volatile("cp.async.ca.shared.global [%0], [%1], 16;"
                 :: "r"(saddr), "l"(gptr) : "memory");
}

__device__ __forceinline__ void cp_async_wait_all() {
    asm volatile("cp.async.commit_group;" ::: "memory");
    asm volatile("cp.async.wait_group 0;" ::: "memory");
}

__device__ __forceinline__ void ldsm_x4(uint32_t* r, uint32_t addr) {
    asm volatile("ldmatrix.sync.aligned.m8n8.x4.shared.b16 {%0,%1,%2,%3}, [%4];"
                 : "=r"(r[0]), "=r"(r[1]), "=r"(r[2]), "=r"(r[3]) : "r"(addr));
}

__device__ __forceinline__ void mma16816(float* c, const uint32_t* a,
                                         uint32_t b0, uint32_t b1) {
    asm volatile(
        "mma.sync.aligned.m16n8k16.row.col.f32.bf16.bf16.f32 "
        "{%0,%1,%2,%3}, {%4,%5,%6,%7}, {%8,%9}, {%0,%1,%2,%3};"
        : "+f"(c[0]), "+f"(c[1]), "+f"(c[2]), "+f"(c[3])
        : "r"(a[0]), "r"(a[1]), "r"(a[2]), "r"(a[3]), "r"(b0), "r"(b1));
}

__device__ __forceinline__ float tanh_relu(float x) {
    x = fmaxf(x, 0.0f);
    float y;
    asm("tanh.approx.f32 %0, %1;" : "=f"(y) : "f"(x));
    return y;
}

// Cumulative tile count for rows < ti: C(ti) = ti*(35-ti)/2.
__device__ __forceinline__ int pair_cum(int ti) { return (ti * (35 - ti)) >> 1; }

// ---------------------------------------------------------------------------
// Pass 2: one CTA (256 thr, 8 warps of 64x32) per upper-triangular 128x128
// tile pair. bf16 3-split gram; mirror tile via conflict-free SMEM transpose.
// cp.async staging; PDL overlaps this prologue with the convert kernel.
// ---------------------------------------------------------------------------
#define ROWB       144                   // smem operand pitch (bytes)
#define TILE_B     (128 * ROWB)          // 18432 B per operand tile
#define SMEM_BYTES (4 * TILE_B)          // 73728 B (covers transpose buffer)
#define TPITCH     132                   // transpose pitch (floats)

__global__ void __launch_bounds__(256, 2)
gram_kernel(float* __restrict__ out) {
    extern __shared__ char smem[];
    const int tid = threadIdx.x;
    const int lid = tid & 31;
    const int wid = tid >> 5;
    const int wr  = wid >> 2;            // warp row 0..1 (64 rows)
    const int wc  = wid & 3;             // warp col 0..3 (32 cols)
    const int b   = blockIdx.y;

    // Closed-form decode of upper-triangular pair index -> (ti, tj), ti <= tj.
    const int bid = blockIdx.x;
    int ti = (int)((35.0f - sqrtf(1225.0f - 8.0f * (float)bid)) * 0.5f);
    if (pair_cum(ti + 1) <= bid) ti++;       // float fixup (at most one step)
    if (pair_cum(ti) > bid)      ti--;
    const int tj = ti + (bid - pair_cum(ti));
    const bool diag = (ti == tj);

    const uint32_t A_HI = 0, A_LO = TILE_B;
    const uint32_t B_HI = diag ? A_HI : 2u * TILE_B;
    const uint32_t B_LO = diag ? A_LO : 3u * TILE_B;

    const uint32_t sb = smem_u32(smem);

    // Precompute everything that does not read the convert outputs.
    const uint32_t a_lane = (uint32_t)(wr * 64 + (lid & 15)) * ROWB + (lid >> 4) * 16;
    const uint32_t b_lane = (uint32_t)(wc * 32 + (lid & 15)) * ROWB + (lid >> 4) * 16;
    const uint32_t aoff_h = sb + A_HI + a_lane;
    const uint32_t aoff_l = sb + A_LO + a_lane;
    const uint32_t boff_h = sb + B_HI + b_lane;
    const uint32_t boff_l = sb + B_LO + b_lane;

    float acc[4][4][4];
#pragma unroll
    for (int mt = 0; mt < 4; mt++)
#pragma unroll
        for (int nt = 0; nt < 4; nt++)
#pragma unroll
            for (int q = 0; q < 4; q++) acc[mt][nt][q] = 0.0f;

    // PDL: wait for the convert kernel's grid (and its stores) to complete.
    cudaGridDependencySynchronize();

    // --- Stage operand tiles via cp.async (128 rows x 128B, pitch 144) -----
    {
        const uint4* hi4 = reinterpret_cast<const uint4*>(g_hi);
        const uint4* lo4 = reinterpret_cast<const uint4*>(g_lo);
        const long baseA = ((long)b * M_PAD + (long)ti * TILE) * 8;
        const long baseB = ((long)b * M_PAD + (long)tj * TILE) * 8;
#pragma unroll
        for (int it = 0; it < 4; it++) {
            int idx = it * 256 + tid;        // 0..1023
            int row = idx >> 3, seg = idx & 7;
            uint32_t so = (uint32_t)(row * ROWB + seg * 16);
            long offA = baseA + row * 8 + seg;
            cp_async16(sb + A_HI + so, hi4 + offA);
            cp_async16(sb + A_LO + so, lo4 + offA);
            if (!diag) {
                long offB = baseB + row * 8 + seg;
                cp_async16(sb + B_HI + so, hi4 + offB);
                cp_async16(sb + B_LO + so, lo4 + offB);
            }
        }
    }
    cp_async_wait_all();
    __syncthreads();

    // Mainloop: acc += Ah*Bh + Ah*Bl + Al*Bh (A fragments reused for 2 of 3)
#pragma unroll
    for (int k = 0; k < 4; k++) {
        uint32_t af[4][4], bh[2][4], bl[2][4];
#pragma unroll
        for (int mt = 0; mt < 4; mt++)
            ldsm_x4(af[mt], aoff_h + mt * 16 * ROWB + k * 32);
#pragma unroll
        for (int bt = 0; bt < 2; bt++) {
            ldsm_x4(bh[bt], boff_h + bt * 16 * ROWB + k * 32);
            ldsm_x4(bl[bt], boff_l + bt * 16 * ROWB + k * 32);
        }
#pragma unroll
        for (int mt = 0; mt < 4; mt++)
#pragma unroll
            for (int nt = 0; nt < 4; nt++) {
                mma16816(acc[mt][nt], af[mt],
                         bh[nt >> 1][nt & 1], bh[nt >> 1][(nt & 1) + 2]);
                mma16816(acc[mt][nt], af[mt],
                         bl[nt >> 1][nt & 1], bl[nt >> 1][(nt & 1) + 2]);
            }
#pragma unroll
        for (int mt = 0; mt < 4; mt++)
            ldsm_x4(af[mt], aoff_l + mt * 16 * ROWB + k * 32);   // reuse af
#pragma unroll
        for (int mt = 0; mt < 4; mt++)
#pragma unroll
            for (int nt = 0; nt < 4; nt++)
                mma16816(acc[mt][nt], af[mt],
                         bh[nt >> 1][nt & 1], bh[nt >> 1][(nt & 1) + 2]);
    }

    // Operand SMEM is dead after ALL warps pass this barrier.
    __syncthreads();

    // --- Epilogue ----------------------------------------------------------
    float* tile_s = reinterpret_cast<float*>(smem);   // [c][r], pitch TPITCH
    const int lrow0 = wr * 64 + (lid >> 2);
    const int lcol0 = wc * 32 + (lid & 3) * 2;
    const long M = M_OUT;
    float* const outb = out + (long)b * M * M;

#pragma unroll
    for (int mt = 0; mt < 4; mt++) {
#pragma unroll
        for (int nt = 0; nt < 4; nt++) {
            int lc = lcol0 + nt * 8;
#pragma unroll
            for (int h = 0; h < 2; h++) {
                int lr = lrow0 + mt * 16 + h * 8;
                float2 v;
                v.x = tanh_relu(acc[mt][nt][h * 2 + 0]);
                v.y = tanh_relu(acc[mt][nt][h * 2 + 1]);
                if (diag) {                    // self loops live on diag tiles
                    if (lr == lc)     v.x += 0.5f;
                    if (lr == lc + 1) v.y += 0.5f;
                }
                int gr = ti * TILE + lr, gc = tj * TILE + lc;
                if (gr < M_OUT && gc < M_OUT)
                    *reinterpret_cast<float2*>(outb + (long)gr * M + gc) = v;
                if (!diag) {                   // transposed copy for mirror
                    tile_s[(lc + 0) * TPITCH + lr] = v.x;   // conflict-free
                    tile_s[(lc + 1) * TPITCH + lr] = v.y;
                }
            }
        }
    }

    if (!diag) {
        __syncthreads();
        // Mirror tile (tj, ti): coalesced float4 stores; conflict-free reads.
#pragma unroll
        for (int it = 0; it < 16; it++) {
            int e  = it * 256 + tid;           // 0..4095 float4 slots
            int c  = e >> 5;                   // 0..127
            int rq = e & 31;
            float4 w = *reinterpret_cast<float4*>(tile_s + c * TPITCH + rq * 4);
            int gr = tj * TILE + c;
            if (gr < M_OUT)
                *reinterpret_cast<float4*>(
                    outb + (long)gr * M + ti * TILE + rq * 4) = w;
        }
    }
}

// ---------------------------------------------------------------------------
extern "C" void kernel_launch(void* const* d_in, const int* in_sizes, int n_in,
                              void* d_out, int out_size) {
    const float* sp = (const float*)d_in[0];
    const float* tp = (const float*)d_in[1];
    if (n_in >= 2 && in_sizes[0] < in_sizes[1]) {
        sp = (const float*)d_in[1];
        tp = (const float*)d_in[0];
    }
    float* out = (float*)d_out;

    const int TOT2 = B_ * M_PAD * 8;
    convert_split_kernel<<<(TOT2 + 255) / 256, 256>>>(
        (const float4*)sp, (const float4*)tp);

    cudaFuncSetAttribute(gram_kernel,
                         cudaFuncAttributeMaxDynamicSharedMemorySize, SMEM_BYTES);

    // PDL launch: gram may begin its prologue while convert is still running;
    // the device-side cudaGridDependencySynchronize() provides the ordering.
    cudaLaunchConfig_t cfg = {};
    cfg.gridDim = dim3(NPAIRS, B_, 1);
    cfg.blockDim = dim3(256, 1, 1);
    cfg.dynamicSmemBytes = SMEM_BYTES;
    cfg.stream = 0;
    cudaLaunchAttribute attrs[1];
    attrs[0].id = cudaLaunchAttributeProgrammaticStreamSerialization;
    attrs[0].val.programmaticStreamSerializationAllowed = 1;
    cfg.attrs = attrs;
    cfg.numAttrs = 1;
    cudaLaunchKernelEx(&cfg, gram_kernel, out);
}

// round 12
// speedup vs baseline: 1.0037x; 1.0037x over previous
#include <cuda_runtime.h>
#include <cuda_bf16.h>
#include <cstdint>

#define B_      16
#define N_SP    2048
#define N_TM    64
#define M_OUT   2112
#define M_PAD   2176
#define KD      64
#define TILE    128
#define NTILES  17
#define NOFF    136      // off-diagonal pairs (ti < tj)
#define NDIAG   17
#define GRID1D  (B_ * (NOFF + NDIAG))    // 2448; off-diag CTAs first

// Scratch: bf16 hi/lo splits of concatenated+padded node embeddings.
__device__ __nv_bfloat16 g_hi[B_ * M_PAD * KD];
__device__ __nv_bfloat16 g_lo[B_ * M_PAD * KD];

// ---------------------------------------------------------------------------
// Pass 1: fp32 -> bf16 hi/lo split, concat(spatial, temporal), zero-pad rows.
// 8 elements (2 float4) per thread; one uint4 store per output array.
// ---------------------------------------------------------------------------
__global__ void convert_split_kernel(const float4* __restrict__ sp,
                                     const float4* __restrict__ tp) {
    const int TOT2 = B_ * M_PAD * 8;     // uint4-granularity work items
    int idx = blockIdx.x * blockDim.x + threadIdx.x;
    if (idx >= TOT2) return;
    int kq2 = idx & 7;                   // 8-elem segment within 64-elem row
    int row = (idx >> 3) % M_PAD;
    int b   = idx / (M_PAD * 8);

    float4 x0 = make_float4(0.f, 0.f, 0.f, 0.f), x1 = x0;
    if (row < N_SP) {
        const float4* p = sp + ((long)b * N_SP + row) * 16 + kq2 * 2;
        x0 = p[0]; x1 = p[1];
    } else if (row < M_OUT) {
        const float4* p = tp + ((long)b * N_TM + (row - N_SP)) * 16 + kq2 * 2;
        x0 = p[0]; x1 = p[1];
    }

    float xf[8] = {x0.x, x0.y, x0.z, x0.w, x1.x, x1.y, x1.z, x1.w};
    union { __nv_bfloat16 h[8]; uint4 u; } uh;
    union { __nv_bfloat16 h[8]; uint4 u; } ul;
#pragma unroll
    for (int i = 0; i < 8; i++) {
        __nv_bfloat16 h = __float2bfloat16(xf[i]);
        float lo = xf[i] - __bfloat162float(h);
        uh.h[i] = h;
        ul.h[i] = __float2bfloat16(lo);
    }
    reinterpret_cast<uint4*>(g_hi)[idx] = uh.u;
    reinterpret_cast<uint4*>(g_lo)[idx] = ul.u;
}

// ---------------------------------------------------------------------------
// PTX helpers (portable compute_103: mma.sync + ldmatrix + cp.async + tanh)
// ---------------------------------------------------------------------------
__device__ __forceinline__ uint32_t smem_u32(const void* p) {
    uint32_t a;
    asm("{ .reg .u64 t; cvta.to.shared.u64 t, %1; cvt.u32.u64 %0, t; }"
        : "=r"(a) : "l"(p));
    return a;
}

__device__ __forceinline__ void cp_async16(uint32_t saddr, const void* gptr) {
    asm volatile("cp.async.ca.shared.global [%0], [%1], 16;"
                 :: "r"(saddr), "l"(gptr) : "memory");
}

__device__ __forceinline__ void cp_async_wait_all() {
    asm volatile("cp.async.commit_group;" ::: "memory");
    asm volatile("cp.async.wait_group 0;" ::: "memory");
}

__device__ __forceinline__ void ldsm_x4(uint32_t* r, uint32_t addr) {
    asm volatile("ldmatrix.sync.aligned.m8n8.x4.shared.b16 {%0,%1,%2,%3}, [%4];"
                 : "=r"(r[0]), "=r"(r[1]), "=r"(r[2]), "=r"(r[3]) : "r"(addr));
}

__device__ __forceinline__ void mma16816(float* c, const uint32_t* a,
                                         uint32_t b0, uint32_t b1) {
    asm volatile(
        "mma.sync.aligned.m16n8k16.row.col.f32.bf16.bf16.f32 "
        "{%0,%1,%2,%3}, {%4,%5,%6,%7}, {%8,%9}, {%0,%1,%2,%3};"
        : "+f"(c[0]), "+f"(c[1]), "+f"(c[2]), "+f"(c[3])
        : "r"(a[0]), "r"(a[1]), "r"(a[2]), "r"(a[3]), "r"(b0), "r"(b1));
}

__device__ __forceinline__ float tanh_relu(float x) {
    x = fmaxf(x, 0.0f);
    float y;
    asm("tanh.approx.f32 %0, %1;" : "=f"(y) : "f"(x));
    return y;
}

// ---------------------------------------------------------------------------
// Pass 2: one CTA (256 thr, 8 warps of 64x32) per 128x128 upper-triangular
// tile. 1D grid: 2176 off-diagonal CTAs first, 272 light diagonal CTAs last
// (cheapest CTAs land in the final partial wave). cp.async staging; bf16
// 3-split mainloop; direct frag stores + conflict-free transpose mirror.
// ---------------------------------------------------------------------------
#define ROWB       144                   // smem operand pitch (bytes)
#define TILE_B     (128 * ROWB)          // 18432 B per operand tile
#define SMEM_BYTES (4 * TILE_B)          // 73728 B (covers transpose buffer)
#define TPITCH     132                   // transpose pitch (floats)

__global__ void __launch_bounds__(256, 2)
gram_kernel(float* __restrict__ out) {
    extern __shared__ char smem[];
    const int tid = threadIdx.x;
    const int lid = tid & 31;
    const int wid = tid >> 5;
    const int wr  = wid >> 2;            // warp row 0..1 (64 rows)
    const int wc  = wid & 3;             // warp col 0..3 (32 cols)

    // Decode 1D CTA id: off-diag block first, then diagonal block.
    int ti, tj, b;
    const int gid = blockIdx.x;
    if (gid < B_ * NOFF) {
        int pid = gid % NOFF;            // off-diagonal pair id
        b = gid / NOFF;
        ti = 0;
        int rem = pid;                   // row ti has (16 - ti) pairs ti<tj
        while (rem >= NTILES - 1 - ti) { rem -= NTILES - 1 - ti; ti++; }
        tj = ti + 1 + rem;
    } else {
        int e = gid - B_ * NOFF;
        ti = tj = e % NDIAG;
        b = e / NDIAG;
    }
    const bool diag = (ti == tj);

    const uint32_t A_HI = 0, A_LO = TILE_B;
    const uint32_t B_HI = diag ? A_HI : 2u * TILE_B;
    const uint32_t B_LO = diag ? A_LO : 3u * TILE_B;

    const uint32_t sb = smem_u32(smem);

    // --- Stage operand tiles via cp.async (128 rows x 128B, pitch 144) -----
    {
        const uint4* hi4 = reinterpret_cast<const uint4*>(g_hi);
        const uint4* lo4 = reinterpret_cast<const uint4*>(g_lo);
        const long baseA = ((long)b * M_PAD + (long)ti * TILE) * 8;
        const long baseB = ((long)b * M_PAD + (long)tj * TILE) * 8;
#pragma unroll
        for (int it = 0; it < 4; it++) {
            int idx = it * 256 + tid;        // 0..1023
            int row = idx >> 3, seg = idx & 7;
            uint32_t so = (uint32_t)(row * ROWB + seg * 16);
            long offA = baseA + row * 8 + seg;
            cp_async16(sb + A_HI + so, hi4 + offA);
            cp_async16(sb + A_LO + so, lo4 + offA);
            if (!diag) {
                long offB = baseB + row * 8 + seg;
                cp_async16(sb + B_HI + so, hi4 + offB);
                cp_async16(sb + B_LO + so, lo4 + offB);
            }
        }
    }
    cp_async_wait_all();
    __syncthreads();

    const uint32_t a_lane = (uint32_t)(wr * 64 + (lid & 15)) * ROWB + (lid >> 4) * 16;
    const uint32_t b_lane = (uint32_t)(wc * 32 + (lid & 15)) * ROWB + (lid >> 4) * 16;
    const uint32_t aoff_h = sb + A_HI + a_lane;
    const uint32_t aoff_l = sb + A_LO + a_lane;
    const uint32_t boff_h = sb + B_HI + b_lane;
    const uint32_t boff_l = sb + B_LO + b_lane;

    float acc[4][4][4];
#pragma unroll
    for (int mt = 0; mt < 4; mt++)
#pragma unroll
        for (int nt = 0; nt < 4; nt++)
#pragma unroll
            for (int q = 0; q < 4; q++) acc[mt][nt][q] = 0.0f;

    // Mainloop: acc += Ah*Bh + Ah*Bl + Al*Bh (A fragments reused for 2 of 3)
#pragma unroll
    for (int k = 0; k < 4; k++) {
        uint32_t af[4][4], bh[2][4], bl[2][4];
#pragma unroll
        for (int mt = 0; mt < 4; mt++)
            ldsm_x4(af[mt], aoff_h + mt * 16 * ROWB + k * 32);
#pragma unroll
        for (int bt = 0; bt < 2; bt++) {
            ldsm_x4(bh[bt], boff_h + bt * 16 * ROWB + k * 32);
            ldsm_x4(bl[bt], boff_l + bt * 16 * ROWB + k * 32);
        }
#pragma unroll
        for (int mt = 0; mt < 4; mt++)
#pragma unroll
            for (int nt = 0; nt < 4; nt++) {
                mma16816(acc[mt][nt], af[mt],
                         bh[nt >> 1][nt & 1], bh[nt >> 1][(nt & 1) + 2]);
                mma16816(acc[mt][nt], af[mt],
                         bl[nt >> 1][nt & 1], bl[nt >> 1][(nt & 1) + 2]);
            }
#pragma unroll
        for (int mt = 0; mt < 4; mt++)
            ldsm_x4(af[mt], aoff_l + mt * 16 * ROWB + k * 32);   // reuse af
#pragma unroll
        for (int mt = 0; mt < 4; mt++)
#pragma unroll
            for (int nt = 0; nt < 4; nt++)
                mma16816(acc[mt][nt], af[mt],
                         bh[nt >> 1][nt & 1], bh[nt >> 1][(nt & 1) + 2]);
    }

    // Operand SMEM is dead after ALL warps pass this barrier.
    __syncthreads();

    // --- Epilogue ----------------------------------------------------------
    float* tile_s = reinterpret_cast<float*>(smem);   // [c][r], pitch TPITCH
    const int lrow0 = wr * 64 + (lid >> 2);
    const int lcol0 = wc * 32 + (lid & 3) * 2;
    const long M = M_OUT;
    float* const outb = out + (long)b * M * M;

#pragma unroll
    for (int mt = 0; mt < 4; mt++) {
#pragma unroll
        for (int nt = 0; nt < 4; nt++) {
            int lc = lcol0 + nt * 8;
#pragma unroll
            for (int h = 0; h < 2; h++) {
                int lr = lrow0 + mt * 16 + h * 8;
                float2 v;
                v.x = tanh_relu(acc[mt][nt][h * 2 + 0]);
                v.y = tanh_relu(acc[mt][nt][h * 2 + 1]);
                if (diag) {                    // self loops live on diag tiles
                    if (lr == lc)     v.x += 0.5f;
                    if (lr == lc + 1) v.y += 0.5f;
                }
                int gr = ti * TILE + lr, gc = tj * TILE + lc;
                if (gr < M_OUT && gc < M_OUT)
                    *reinterpret_cast<float2*>(outb + (long)gr * M + gc) = v;
                if (!diag) {                   // transposed copy for mirror
                    tile_s[(lc + 0) * TPITCH + lr] = v.x;   // conflict-free
                    tile_s[(lc + 1) * TPITCH + lr] = v.y;
                }
            }
        }
    }

    if (!diag) {
        __syncthreads();
        // Mirror tile (tj, ti): coalesced float4 stores; conflict-free reads.
#pragma unroll
        for (int it = 0; it < 16; it++) {
            int e  = it * 256 + tid;           // 0..4095 float4 slots
            int c  = e >> 5;                   // 0..127
            int rq = e & 31;
            float4 w = *reinterpret_cast<float4*>(tile_s + c * TPITCH + rq * 4);
            int gr = tj * TILE + c;
            if (gr < M_OUT)
                *reinterpret_cast<float4*>(
                    outb + (long)gr * M + ti * TILE + rq * 4) = w;
        }
    }
}

// ---------------------------------------------------------------------------
extern "C" void kernel_launch(void* const* d_in, const int* in_sizes, int n_in,
                              void* d_out, int out_size) {
    const float* sp = (const float*)d_in[0];
    const float* tp = (const float*)d_in[1];
    if (n_in >= 2 && in_sizes[0] < in_sizes[1]) {
        sp = (const float*)d_in[1];
        tp = (const float*)d_in[0];
    }
    float* out = (float*)d_out;

    const int TOT2 = B_ * M_PAD * 8;
    convert_split_kernel<<<(TOT2 + 255) / 256, 256>>>(
        (const float4*)sp, (const float4*)tp);

    cudaFuncSetAttribute(gram_kernel,
                         cudaFuncAttributeMaxDynamicSharedMemorySize, SMEM_BYTES);
    gram_kernel<<<GRID1D, 256, SMEM_BYTES>>>(out);
}